// round 3
// baseline (speedup 1.0000x reference)
#include <cuda_runtime.h>

#define N_  2048
#define L_  2
#define H_  4
#define D_  16
#define F_  64
#define E_  64
#define C_  32
#define NL_ (N_*L_)             // 4096
#define NLH (N_*L_*H_)          // 16384
#define EPS 1e-5f

// Scratch (device globals — no allocation allowed)
__device__ float g_logits[NLH];            // 64 KB
__device__ float g_value [NLH * D_];       // 1 MB
__device__ float g_attn_scratch[C_ * NLH]; // 2 MB (zero-init; only matching entries ever written)
__device__ float g_max [C_ * H_];
__device__ float g_rinv[C_ * H_];
__device__ int   g_comp[N_];               // normalized int32 component ids

// ---------------------------------------------------------------------------
__device__ __forceinline__ float warp_sum16(float v) {
    v += __shfl_xor_sync(0xffffffffu, v, 1);
    v += __shfl_xor_sync(0xffffffffu, v, 2);
    v += __shfl_xor_sync(0xffffffffu, v, 4);
    v += __shfl_xor_sync(0xffffffffu, v, 8);
    return v;
}

__device__ __forceinline__ float dot4(float4 w, float4 f) {
    return fmaf(w.x, f.x, fmaf(w.y, f.y, fmaf(w.z, f.z, w.w * f.w)));
}

// ---------------------------------------------------------------------------
// Kernel 1: per-node FFNs, key + value paths interleaved for 2x MLP and
// overlapping shfl-reduction chains. One warp per (n,l,h).
// Weight access pattern per step: one LDG.128 across warp = 512B contiguous
// (w0, two rows), one LDG.32 across warp = one 128B line (w1, two rows).
// ---------------------------------------------------------------------------
__global__ __launch_bounds__(128) void ffn_kernel(
    const float* __restrict__ feat,  const float* __restrict__ query,
    const float* __restrict__ kw0,   const float* __restrict__ kb0,
    const float* __restrict__ kw1,   const float* __restrict__ kb1,
    const float* __restrict__ vw0,   const float* __restrict__ vb0,
    const float* __restrict__ vw1,   const float* __restrict__ vb1,
    const float* __restrict__ key_gamma, const float* __restrict__ key_beta)
{
    const int nl   = blockIdx.x;
    const int wid  = threadIdx.x >> 5;
    const int lane = threadIdx.x & 31;
    const int l16  = lane & 15;
    const int half = lane >> 4;
    const int nlh  = nl * H_ + wid;

    const float4 f4 = ((const float4*)(feat + (size_t)nl * E_))[l16];
    const float gd = key_gamma[l16];
    const float bd = key_beta [l16];

    const size_t o0 = (size_t)nlh * (F_ * E_);
    const size_t o1 = (size_t)nlh * (F_ * D_);
    const size_t ob = (size_t)nlh * F_;
    const size_t od = (size_t)nlh * D_;

    const float* kw0p = kw0 + o0 + half * E_ + l16 * 4;
    const float* vw0p = vw0 + o0 + half * E_ + l16 * 4;
    const float* kw1p = kw1 + o1 + half * D_ + l16;
    const float* vw1p = vw1 + o1 + half * D_ + l16;

    const float kb0a = kb0[ob + lane],      kb0b = kb0[ob + 32 + lane];
    const float vb0a = vb0[ob + lane],      vb0b = vb0[ob + 32 + lane];

    float accK = 0.f, accV = 0.f;
#pragma unroll
    for (int s = 0; s < 32; s++) {
        float4 wk = __ldcs((const float4*)(kw0p + s * 2 * E_));
        float4 wv = __ldcs((const float4*)(vw0p + s * 2 * E_));
        float w1k = __ldcs(kw1p + s * 2 * D_);
        float w1v = __ldcs(vw1p + s * 2 * D_);

        float tk = warp_sum16(dot4(wk, f4));   // two independent shfl chains
        float tv = warp_sum16(dot4(wv, f4));

        float bK = __shfl_sync(0xffffffffu, (s < 16) ? kb0a : kb0b, 2*s + half);
        float bV = __shfl_sync(0xffffffffu, (s < 16) ? vb0a : vb0b, 2*s + half);

        accK = fmaf(fmaxf(tk + bK, 0.f), w1k, accK);
        accV = fmaf(fmaxf(tv + bV, 0.f), w1v, accV);
    }

    // combine even-f (lanes 0-15) and odd-f (lanes 16-31) partials
    float xK = accK + __shfl_xor_sync(0xffffffffu, accK, 16) + kb1[od + l16];
    float xV = accV + __shfl_xor_sync(0xffffffffu, accV, 16) + vb1[od + l16];

    // LayerNorm over 16 d-values (replicated in both halves); ref reuses key LN
    float muK  = warp_sum16(xK) * (1.f/16.f);
    float dlK  = xK - muK;
    float varK = warp_sum16(dlK * dlK) * (1.f/16.f);
    float kln  = fmaf(dlK * rsqrtf(varK + EPS), gd, bd);

    float muV  = warp_sum16(xV) * (1.f/16.f);
    float dlV  = xV - muV;
    float varV = warp_sum16(dlV * dlV) * (1.f/16.f);
    float vln  = fmaf(dlV * rsqrtf(varV + EPS), gd, bd);

    float p = warp_sum16(kln * query[od + l16]);
    if (lane == 0) g_logits[nlh] = p;
    if (lane < D_) g_value[od + lane] = vln;
}

// ---------------------------------------------------------------------------
// Kernel 2: per-(c,h) softmax statistics. grid = C*H = 128 blocks.
// Block 0 also normalizes component ids to int32 (dtype auto-detected).
// ---------------------------------------------------------------------------
__global__ __launch_bounds__(256) void stats_kernel(const int* __restrict__ comp)
{
    const int c = blockIdx.x >> 2;
    const int h = blockIdx.x & 3;
    const int t = threadIdx.x;

    __shared__ int   s_nz;
    __shared__ float red[256];
    __shared__ float smx;

    // dtype detection: int64 iff all odd 32-bit words in the first N_ words
    // are zero (values in [0,32); reads in-bounds for both dtypes).
    if (t == 0) s_nz = 0;
    __syncthreads();
    {
        int vz = 0;
        for (int i = t; i < N_/2; i += 256) vz |= comp[2*i + 1];
        if (vz) atomicOr(&s_nz, 1);
    }
    __syncthreads();
    const int is64 = (s_nz == 0);

    if (blockIdx.x == 0)
        for (int n = t; n < N_; n += 256)
            g_comp[n] = is64 ? comp[2*n] : comp[n];

    // pass 1: max over matching logits of this head
    float m = -3.0e38f;
    for (int j = t; j < NL_; j += 256) {
        int n = j >> 1;
        int cid = is64 ? comp[2*n] : comp[n];
        if (cid == c) m = fmaxf(m, g_logits[j * H_ + h]);
    }
    red[t] = m; __syncthreads();
    for (int s = 128; s >= 1; s >>= 1) {
        if (t < s) red[t] = fmaxf(red[t], red[t + s]);
        __syncthreads();
    }
    if (t == 0) smx = red[0];
    __syncthreads();
    const float mx = smx;

    // pass 2: exp-sum over matching logits
    float ss = 0.f;
    for (int j = t; j < NL_; j += 256) {
        int n = j >> 1;
        int cid = is64 ? comp[2*n] : comp[n];
        if (cid == c) ss += __expf(g_logits[j * H_ + h] - mx);
    }
    red[t] = ss; __syncthreads();
    for (int s = 128; s >= 1; s >>= 1) {
        if (t < s) red[t] += red[t + s];
        __syncthreads();
    }
    if (t == 0) {
        g_max [blockIdx.x] = mx;
        g_rinv[blockIdx.x] = 1.f / red[0];
    }
}

// ---------------------------------------------------------------------------
// Kernel 3: sparse attn scatter — each (n,l,h) writes its one nonzero entry.
// Everything else in the attn tensor is zero (memset / zero-init scratch).
// ---------------------------------------------------------------------------
__global__ __launch_bounds__(256) void attn_kernel(float* __restrict__ attn_base)
{
    const int idx = blockIdx.x * 256 + threadIdx.x;
    const int n   = idx >> 3;
    const int h   = idx & 3;
    const int ch  = g_comp[n] * H_ + h;
    float e = __expf(g_logits[idx] - g_max[ch]) * g_rinv[ch];
    attn_base[(size_t)g_comp[n] * NLH + idx] = e;
}

// ---------------------------------------------------------------------------
// Kernel 4: out[c,h,d] = sum(attn * value), final LayerNorm, uid.
// grid = C blocks, 256 threads; thread t handles head h = t & 3.
// Skips value loads where attn == 0 (~31/32 of entries).
// ---------------------------------------------------------------------------
__global__ __launch_bounds__(256) void out_kernel(
    const float* __restrict__ attn_base,
    const float* __restrict__ out_gamma, const float* __restrict__ out_beta,
    float* __restrict__ out, float* __restrict__ uid_out, int write_uid)
{
    const int c = blockIdx.x;
    const int t = threadIdx.x;

    __shared__ float sacc[256 * 17];

    const float* attn_c = attn_base + (size_t)c * NLH;

    float acc[D_];
#pragma unroll
    for (int d = 0; d < D_; d++) acc[d] = 0.f;

    for (int idx = t; idx < NLH; idx += 256) {
        float a = attn_c[idx];
        if (a != 0.f) {
            const float4* v4 = (const float4*)(g_value + (size_t)idx * D_);
            float4 va = v4[0], vb = v4[1], vc = v4[2], vd = v4[3];
            acc[0]  = fmaf(a, va.x, acc[0]);  acc[1]  = fmaf(a, va.y, acc[1]);
            acc[2]  = fmaf(a, va.z, acc[2]);  acc[3]  = fmaf(a, va.w, acc[3]);
            acc[4]  = fmaf(a, vb.x, acc[4]);  acc[5]  = fmaf(a, vb.y, acc[5]);
            acc[6]  = fmaf(a, vb.z, acc[6]);  acc[7]  = fmaf(a, vb.w, acc[7]);
            acc[8]  = fmaf(a, vc.x, acc[8]);  acc[9]  = fmaf(a, vc.y, acc[9]);
            acc[10] = fmaf(a, vc.z, acc[10]); acc[11] = fmaf(a, vc.w, acc[11]);
            acc[12] = fmaf(a, vd.x, acc[12]); acc[13] = fmaf(a, vd.y, acc[13]);
            acc[14] = fmaf(a, vd.z, acc[14]); acc[15] = fmaf(a, vd.w, acc[15]);
        }
    }

#pragma unroll
    for (int d = 0; d < D_; d++) sacc[t*17 + d] = acc[d];
    __syncthreads();
    for (int s = 128; s >= 4; s >>= 1) {
        if (t < s) {
#pragma unroll
            for (int d = 0; d < D_; d++) sacc[t*17 + d] += sacc[(t+s)*17 + d];
        }
        __syncthreads();
    }
    // sacc[h*17 + d] holds out[c,h,d] (attn already normalized)

    if (t < 64) {
        int hh = t >> 4, d = t & 15;
        float x = sacc[hh*17 + d];
        float s1 = x;
#pragma unroll
        for (int off = 8; off >= 1; off >>= 1) s1 += __shfl_xor_sync(0xffffffffu, s1, off);
        float mu = s1 * (1.f/16.f);
        float dl = x - mu;
        float vv = dl * dl;
#pragma unroll
        for (int off = 8; off >= 1; off >>= 1) vv += __shfl_xor_sync(0xffffffffu, vv, off);
        float var = vv * (1.f/16.f);
        out[c * (H_*D_) + hh*D_ + d] = fmaf(dl * rsqrtf(var + EPS), out_gamma[d], out_beta[d]);
    }

    if (write_uid && t == 0) uid_out[c] = (float)c;
}

// ---------------------------------------------------------------------------
extern "C" void kernel_launch(void* const* d_in, const int* in_sizes, int n_in,
                              void* d_out, int out_size) {
    const float* feat      = (const float*)d_in[0];
    const float* query     = (const float*)d_in[1];
    const float* kw0       = (const float*)d_in[2];
    const float* kb0       = (const float*)d_in[3];
    const float* kw1       = (const float*)d_in[4];
    const float* kb1       = (const float*)d_in[5];
    const float* vw0       = (const float*)d_in[6];
    const float* vb0       = (const float*)d_in[7];
    const float* vw1       = (const float*)d_in[8];
    const float* vb1       = (const float*)d_in[9];
    const float* key_gamma = (const float*)d_in[10];
    const float* key_beta  = (const float*)d_in[11];
    const float* out_gamma = (const float*)d_in[12];
    const float* out_beta  = (const float*)d_in[13];
    const int*   comp      = (const int*)  d_in[14];   // int32 or int64; detected on device

    float* out = (float*)d_out;

    const int SZ_OUT  = C_ * H_ * D_;      // 2048
    const int SZ_ATTN = C_ * NLH;          // 524288
    const int full_attn = (out_size >= SZ_OUT + SZ_ATTN) ? 1 : 0;
    const int full_uid  = (out_size >= SZ_OUT + SZ_ATTN + C_) ? 1 : 0;

    float* attn_base;
    if (full_attn) {
        attn_base = out + SZ_OUT;
        // d_out is poisoned before timing; zero the (sparse) attn region.
        cudaMemsetAsync(attn_base, 0, (size_t)SZ_ATTN * sizeof(float), 0);
    } else {
        // device-global scratch: zero-initialized at load; only matching
        // entries are ever written (same set, same values every call).
        cudaMemsetAsync(g_attn_scratch, 0, 0, 0); // no-op keeps path uniform
        attn_base = nullptr;                      // patched below
    }

    ffn_kernel<<<N_ * L_, 128>>>(feat, query, kw0, kb0, kw1, kb1,
                                 vw0, vb0, vw1, vb1, key_gamma, key_beta);

    stats_kernel<<<C_ * H_, 256>>>(comp);

    if (!full_attn) {
        // resolve device-symbol address without allocation
        void* p = nullptr;
        cudaGetSymbolAddress(&p, g_attn_scratch);
        attn_base = (float*)p;
    }

    attn_kernel<<<NLH / 256, 256>>>(attn_base);

    float* uid_out = full_uid ? (out + SZ_OUT + SZ_ATTN) : (float*)nullptr;
    out_kernel<<<C_, 256>>>(attn_base, out_gamma, out_beta, out, uid_out, full_uid);
}

// round 5
// speedup vs baseline: 1.0274x; 1.0274x over previous
#include <cuda_runtime.h>

#define N_  2048
#define L_  2
#define H_  4
#define D_  16
#define F_  64
#define E_  64
#define C_  32
#define NL_ (N_*L_)             // 4096
#define NLH (N_*L_*H_)          // 16384
#define EPS 1e-5f

// Scratch (device globals — no allocation allowed)
__device__ float g_logits[NLH];            // 64 KB
__device__ float g_value [NLH * D_];       // 1 MB
__device__ float g_attn_scratch[C_ * NLH]; // 2 MB fallback if attn not in d_out
__device__ float g_max [C_ * H_];
__device__ float g_rinv[C_ * H_];
__device__ int   g_comp[N_];               // normalized int32 component ids

// ---------------------------------------------------------------------------
__device__ __forceinline__ float warp_sum16(float v) {
    v += __shfl_xor_sync(0xffffffffu, v, 1);
    v += __shfl_xor_sync(0xffffffffu, v, 2);
    v += __shfl_xor_sync(0xffffffffu, v, 4);
    v += __shfl_xor_sync(0xffffffffu, v, 8);
    return v;
}

__device__ __forceinline__ float dot4(float4 w, float4 f) {
    return fmaf(w.x, f.x, fmaf(w.y, f.y, fmaf(w.z, f.z, w.w * f.w)));
}

// ---------------------------------------------------------------------------
// Kernel 1: per-node FFNs, key + value paths interleaved. One warp per (n,l,h).
// Per step: one LDG.128 across warp = 512B contiguous (w0, two rows) per path,
// one LDG.32 across warp = one 128B line (w1, two rows) per path.
// ---------------------------------------------------------------------------
__global__ __launch_bounds__(128) void ffn_kernel(
    const float* __restrict__ feat,  const float* __restrict__ query,
    const float* __restrict__ kw0,   const float* __restrict__ kb0,
    const float* __restrict__ kw1,   const float* __restrict__ kb1,
    const float* __restrict__ vw0,   const float* __restrict__ vb0,
    const float* __restrict__ vw1,   const float* __restrict__ vb1,
    const float* __restrict__ key_gamma, const float* __restrict__ key_beta)
{
    const int nl   = blockIdx.x;
    const int wid  = threadIdx.x >> 5;
    const int lane = threadIdx.x & 31;
    const int l16  = lane & 15;
    const int half = lane >> 4;
    const int nlh  = nl * H_ + wid;

    const float4 f4 = ((const float4*)(feat + (size_t)nl * E_))[l16];
    const float gd = key_gamma[l16];
    const float bd = key_beta [l16];

    const size_t o0 = (size_t)nlh * (F_ * E_);
    const size_t o1 = (size_t)nlh * (F_ * D_);
    const size_t ob = (size_t)nlh * F_;
    const size_t od = (size_t)nlh * D_;

    const float* kw0p = kw0 + o0 + half * E_ + l16 * 4;
    const float* vw0p = vw0 + o0 + half * E_ + l16 * 4;
    const float* kw1p = kw1 + o1 + half * D_ + l16;
    const float* vw1p = vw1 + o1 + half * D_ + l16;

    const float kb0a = kb0[ob + lane],      kb0b = kb0[ob + 32 + lane];
    const float vb0a = vb0[ob + lane],      vb0b = vb0[ob + 32 + lane];

    float accK = 0.f, accV = 0.f;
#pragma unroll
    for (int s = 0; s < 32; s++) {
        float4 wk = __ldcs((const float4*)(kw0p + s * 2 * E_));
        float4 wv = __ldcs((const float4*)(vw0p + s * 2 * E_));
        float w1k = __ldcs(kw1p + s * 2 * D_);
        float w1v = __ldcs(vw1p + s * 2 * D_);

        float tk = warp_sum16(dot4(wk, f4));   // two independent shfl chains
        float tv = warp_sum16(dot4(wv, f4));

        float bK = __shfl_sync(0xffffffffu, (s < 16) ? kb0a : kb0b, 2*s + half);
        float bV = __shfl_sync(0xffffffffu, (s < 16) ? vb0a : vb0b, 2*s + half);

        accK = fmaf(fmaxf(tk + bK, 0.f), w1k, accK);
        accV = fmaf(fmaxf(tv + bV, 0.f), w1v, accV);
    }

    float xK = accK + __shfl_xor_sync(0xffffffffu, accK, 16) + kb1[od + l16];
    float xV = accV + __shfl_xor_sync(0xffffffffu, accV, 16) + vb1[od + l16];

    // LayerNorm over 16 d-values (both halves replicated); ref reuses key LN
    float muK  = warp_sum16(xK) * (1.f/16.f);
    float dlK  = xK - muK;
    float varK = warp_sum16(dlK * dlK) * (1.f/16.f);
    float kln  = fmaf(dlK * rsqrtf(varK + EPS), gd, bd);

    float muV  = warp_sum16(xV) * (1.f/16.f);
    float dlV  = xV - muV;
    float varV = warp_sum16(dlV * dlV) * (1.f/16.f);
    float vln  = fmaf(dlV * rsqrtf(varV + EPS), gd, bd);

    float p = warp_sum16(kln * query[od + l16]);
    if (lane == 0) g_logits[nlh] = p;
    if (lane < D_) g_value[od + lane] = vln;
}

// ---------------------------------------------------------------------------
// Kernel 2: per-(c,h) softmax statistics. grid = C*H = 128 blocks.
// Block 0 also normalizes component ids to int32 (dtype auto-detected).
// ---------------------------------------------------------------------------
__global__ __launch_bounds__(256) void stats_kernel(const int* __restrict__ comp)
{
    const int c = blockIdx.x >> 2;
    const int h = blockIdx.x & 3;
    const int t = threadIdx.x;

    __shared__ int   s_nz;
    __shared__ float red[256];
    __shared__ float smx;

    // dtype detection: int64 iff all odd 32-bit words in the first N_ words
    // are zero (values in [0,32); reads in-bounds for both dtypes).
    if (t == 0) s_nz = 0;
    __syncthreads();
    {
        int vz = 0;
        for (int i = t; i < N_/2; i += 256) vz |= comp[2*i + 1];
        if (vz) atomicOr(&s_nz, 1);
    }
    __syncthreads();
    const int is64 = (s_nz == 0);

    if (blockIdx.x == 0)
        for (int n = t; n < N_; n += 256)
            g_comp[n] = is64 ? comp[2*n] : comp[n];

    // pass 1: max over matching logits of this head
    float m = -3.0e38f;
    for (int j = t; j < NL_; j += 256) {
        int n = j >> 1;
        int cid = is64 ? comp[2*n] : comp[n];
        if (cid == c) m = fmaxf(m, g_logits[j * H_ + h]);
    }
    red[t] = m; __syncthreads();
    for (int s = 128; s >= 1; s >>= 1) {
        if (t < s) red[t] = fmaxf(red[t], red[t + s]);
        __syncthreads();
    }
    if (t == 0) smx = red[0];
    __syncthreads();
    const float mx = smx;

    // pass 2: exp-sum over matching logits
    float ss = 0.f;
    for (int j = t; j < NL_; j += 256) {
        int n = j >> 1;
        int cid = is64 ? comp[2*n] : comp[n];
        if (cid == c) ss += __expf(g_logits[j * H_ + h] - mx);
    }
    red[t] = ss; __syncthreads();
    for (int s = 128; s >= 1; s >>= 1) {
        if (t < s) red[t] += red[t + s];
        __syncthreads();
    }
    if (t == 0) {
        g_max [blockIdx.x] = mx;
        g_rinv[blockIdx.x] = 1.f / red[0];
    }
}

// ---------------------------------------------------------------------------
// Kernel 3: sparse attn scatter — each (n,l,h) writes its one nonzero entry.
// Everything else in the attn tensor is zero (async memset).
// ---------------------------------------------------------------------------
__global__ __launch_bounds__(256) void attn_kernel(float* __restrict__ attn_base)
{
    const int idx = blockIdx.x * 256 + threadIdx.x;
    const int n   = idx >> 3;
    const int h   = idx & 3;
    const int ch  = g_comp[n] * H_ + h;
    float e = __expf(g_logits[idx] - g_max[ch]) * g_rinv[ch];
    attn_base[(size_t)g_comp[n] * NLH + idx] = e;
}

// ---------------------------------------------------------------------------
// Kernel 4: direct gather — out[c,h,d] = sum over matching (n,l) of
// softmax-weight * value, computed from logits/stats (all L2-hot; never
// touches the materialized attn tensor). Final LayerNorm fused per block.
// grid = C*H = 128 blocks, 256 threads.
// ---------------------------------------------------------------------------
__global__ __launch_bounds__(256) void out_kernel(
    const float* __restrict__ out_gamma, const float* __restrict__ out_beta,
    float* __restrict__ out, float* __restrict__ uid_out, int write_uid)
{
    const int c = blockIdx.x >> 2;
    const int h = blockIdx.x & 3;
    const int t = threadIdx.x;

    __shared__ float sacc[256 * 17];

    const float mx   = g_max [blockIdx.x];
    const float rinv = g_rinv[blockIdx.x];

    float acc[D_];
#pragma unroll
    for (int d = 0; d < D_; d++) acc[d] = 0.f;

    for (int j = t; j < NL_; j += 256) {
        int n = j >> 1;
        if (g_comp[n] == c) {
            int idx = j * H_ + h;
            float e = __expf(g_logits[idx] - mx);
            const float4* v4 = (const float4*)(g_value + (size_t)idx * D_);
            float4 va = v4[0], vb = v4[1], vc = v4[2], vd = v4[3];
            acc[0]  = fmaf(e, va.x, acc[0]);  acc[1]  = fmaf(e, va.y, acc[1]);
            acc[2]  = fmaf(e, va.z, acc[2]);  acc[3]  = fmaf(e, va.w, acc[3]);
            acc[4]  = fmaf(e, vb.x, acc[4]);  acc[5]  = fmaf(e, vb.y, acc[5]);
            acc[6]  = fmaf(e, vb.z, acc[6]);  acc[7]  = fmaf(e, vb.w, acc[7]);
            acc[8]  = fmaf(e, vc.x, acc[8]);  acc[9]  = fmaf(e, vc.y, acc[9]);
            acc[10] = fmaf(e, vc.z, acc[10]); acc[11] = fmaf(e, vc.w, acc[11]);
            acc[12] = fmaf(e, vd.x, acc[12]); acc[13] = fmaf(e, vd.y, acc[13]);
            acc[14] = fmaf(e, vd.z, acc[14]); acc[15] = fmaf(e, vd.w, acc[15]);
        }
    }

#pragma unroll
    for (int d = 0; d < D_; d++) sacc[t*17 + d] = acc[d];
    __syncthreads();
    for (int s = 128; s >= 1; s >>= 1) {
        if (t < s) {
#pragma unroll
            for (int d = 0; d < D_; d++) sacc[t*17 + d] += sacc[(t+s)*17 + d];
        }
        __syncthreads();
    }
    // sacc[0*17 + d] holds the un-rinv'd out[c,h,d]

    // final LayerNorm over d (16 values) in the first warp
    if (t < 16) {
        float x = sacc[t] * rinv;                 // sacc[0*17 + t]
        float mu = warp_sum16(x) * (1.f/16.f);
        float dl = x - mu;
        float var = warp_sum16(dl * dl) * (1.f/16.f);
        out[c * (H_*D_) + h * D_ + t] =
            fmaf(dl * rsqrtf(var + EPS), out_gamma[t], out_beta[t]);
    }

    // one h==0 block exists for every c in [0,C): blockIdx.x = 4c
    if (write_uid && h == 0 && t == 0)
        uid_out[c] = (float)c;
}

// ---------------------------------------------------------------------------
extern "C" void kernel_launch(void* const* d_in, const int* in_sizes, int n_in,
                              void* d_out, int out_size) {
    const float* feat      = (const float*)d_in[0];
    const float* query     = (const float*)d_in[1];
    const float* kw0       = (const float*)d_in[2];
    const float* kb0       = (const float*)d_in[3];
    const float* kw1       = (const float*)d_in[4];
    const float* kb1       = (const float*)d_in[5];
    const float* vw0       = (const float*)d_in[6];
    const float* vb0       = (const float*)d_in[7];
    const float* vw1       = (const float*)d_in[8];
    const float* vb1       = (const float*)d_in[9];
    const float* key_gamma = (const float*)d_in[10];
    const float* key_beta  = (const float*)d_in[11];
    const float* out_gamma = (const float*)d_in[12];
    const float* out_beta  = (const float*)d_in[13];
    const int*   comp      = (const int*)  d_in[14];   // int32 or int64; detected on device

    float* out = (float*)d_out;

    const int SZ_OUT  = C_ * H_ * D_;      // 2048
    const int SZ_ATTN = C_ * NLH;          // 524288
    const int full_attn = (out_size >= SZ_OUT + SZ_ATTN) ? 1 : 0;
    const int full_uid  = (out_size >= SZ_OUT + SZ_ATTN + C_) ? 1 : 0;

    float* attn_base;
    if (full_attn) {
        attn_base = out + SZ_OUT;
    } else {
        void* p = nullptr;
        cudaGetSymbolAddress(&p, g_attn_scratch);
        attn_base = (float*)p;
    }
    // d_out is poisoned before timing; zero the (sparse) attn region.
    cudaMemsetAsync(attn_base, 0, (size_t)SZ_ATTN * sizeof(float), 0);

    ffn_kernel<<<N_ * L_, 128>>>(feat, query, kw0, kb0, kw1, kb1,
                                 vw0, vb0, vw1, vb1, key_gamma, key_beta);

    stats_kernel<<<C_ * H_, 256>>>(comp);

    attn_kernel<<<NLH / 256, 256>>>(attn_base);

    float* uid_out = full_uid ? (out + SZ_OUT + SZ_ATTN) : (float*)nullptr;
    out_kernel<<<C_ * H_, 256>>>(out_gamma, out_beta, out, uid_out, full_uid);
}

// round 6
// speedup vs baseline: 1.1347x; 1.1045x over previous
#include <cuda_runtime.h>

#define N_  2048
#define L_  2
#define H_  4
#define D_  16
#define F_  64
#define E_  64
#define C_  32
#define NL_ (N_*L_)             // 4096
#define NLH (N_*L_*H_)          // 16384
#define EPS 1e-5f

// Scratch (device globals — no allocation allowed)
__device__ float g_logits[NLH];            // 64 KB
__device__ float g_value [NLH * D_];       // 1 MB
__device__ float g_attn_scratch[C_ * NLH]; // 2 MB fallback if attn not in d_out

// ---------------------------------------------------------------------------
__device__ __forceinline__ float warp_sum16(float v) {
    v += __shfl_xor_sync(0xffffffffu, v, 1);
    v += __shfl_xor_sync(0xffffffffu, v, 2);
    v += __shfl_xor_sync(0xffffffffu, v, 4);
    v += __shfl_xor_sync(0xffffffffu, v, 8);
    return v;
}

__device__ __forceinline__ float warp_sum32(float v) {
    v += __shfl_xor_sync(0xffffffffu, v, 16);
    return warp_sum16(v);
}

__device__ __forceinline__ float warp_max32(float v) {
    v = fmaxf(v, __shfl_xor_sync(0xffffffffu, v, 16));
    v = fmaxf(v, __shfl_xor_sync(0xffffffffu, v, 8));
    v = fmaxf(v, __shfl_xor_sync(0xffffffffu, v, 4));
    v = fmaxf(v, __shfl_xor_sync(0xffffffffu, v, 2));
    v = fmaxf(v, __shfl_xor_sync(0xffffffffu, v, 1));
    return v;
}

__device__ __forceinline__ float dot4(float4 w, float4 f) {
    return fmaf(w.x, f.x, fmaf(w.y, f.y, fmaf(w.z, f.z, w.w * f.w)));
}

// ---------------------------------------------------------------------------
// Kernel 1: per-node FFNs, key + value paths interleaved. One warp per (n,l,h).
// Per step: one LDG.128 across warp = 512B contiguous (w0, two rows) per path,
// one LDG.32 across warp = one 128B line (w1, two rows) per path.
// ---------------------------------------------------------------------------
__global__ __launch_bounds__(128) void ffn_kernel(
    const float* __restrict__ feat,  const float* __restrict__ query,
    const float* __restrict__ kw0,   const float* __restrict__ kb0,
    const float* __restrict__ kw1,   const float* __restrict__ kb1,
    const float* __restrict__ vw0,   const float* __restrict__ vb0,
    const float* __restrict__ vw1,   const float* __restrict__ vb1,
    const float* __restrict__ key_gamma, const float* __restrict__ key_beta)
{
    const int nl   = blockIdx.x;
    const int wid  = threadIdx.x >> 5;
    const int lane = threadIdx.x & 31;
    const int l16  = lane & 15;
    const int half = lane >> 4;
    const int nlh  = nl * H_ + wid;

    const float4 f4 = ((const float4*)(feat + (size_t)nl * E_))[l16];
    const float gd = key_gamma[l16];
    const float bd = key_beta [l16];

    const size_t o0 = (size_t)nlh * (F_ * E_);
    const size_t o1 = (size_t)nlh * (F_ * D_);
    const size_t ob = (size_t)nlh * F_;
    const size_t od = (size_t)nlh * D_;

    const float* kw0p = kw0 + o0 + half * E_ + l16 * 4;
    const float* vw0p = vw0 + o0 + half * E_ + l16 * 4;
    const float* kw1p = kw1 + o1 + half * D_ + l16;
    const float* vw1p = vw1 + o1 + half * D_ + l16;

    const float kb0a = kb0[ob + lane],      kb0b = kb0[ob + 32 + lane];
    const float vb0a = vb0[ob + lane],      vb0b = vb0[ob + 32 + lane];

    float accK = 0.f, accV = 0.f;
#pragma unroll
    for (int s = 0; s < 32; s++) {
        float4 wk = __ldcs((const float4*)(kw0p + s * 2 * E_));
        float4 wv = __ldcs((const float4*)(vw0p + s * 2 * E_));
        float w1k = __ldcs(kw1p + s * 2 * D_);
        float w1v = __ldcs(vw1p + s * 2 * D_);

        float tk = warp_sum16(dot4(wk, f4));   // two independent shfl chains
        float tv = warp_sum16(dot4(wv, f4));

        float bK = __shfl_sync(0xffffffffu, (s < 16) ? kb0a : kb0b, 2*s + half);
        float bV = __shfl_sync(0xffffffffu, (s < 16) ? vb0a : vb0b, 2*s + half);

        accK = fmaf(fmaxf(tk + bK, 0.f), w1k, accK);
        accV = fmaf(fmaxf(tv + bV, 0.f), w1v, accV);
    }

    float xK = accK + __shfl_xor_sync(0xffffffffu, accK, 16) + kb1[od + l16];
    float xV = accV + __shfl_xor_sync(0xffffffffu, accV, 16) + vb1[od + l16];

    // LayerNorm over 16 d-values (both halves replicated); ref reuses key LN
    float muK  = warp_sum16(xK) * (1.f/16.f);
    float dlK  = xK - muK;
    float varK = warp_sum16(dlK * dlK) * (1.f/16.f);
    float kln  = fmaf(dlK * rsqrtf(varK + EPS), gd, bd);

    float muV  = warp_sum16(xV) * (1.f/16.f);
    float dlV  = xV - muV;
    float varV = warp_sum16(dlV * dlV) * (1.f/16.f);
    float vln  = fmaf(dlV * rsqrtf(varV + EPS), gd, bd);

    float p = warp_sum16(kln * query[od + l16]);
    if (lane == 0) g_logits[nlh] = p;
    if (lane < D_) g_value[od + lane] = vln;
}

// ---------------------------------------------------------------------------
// Kernel 2 (fused epilogue): one block per (c,h); zero cross-block deps.
// Each block: dtype-detect, smem match mask, softmax stats over its 4096
// logits, sparse attn writes (rinv folded in), weighted value gather, LN.
// grid = C*H = 128 blocks, 256 threads.
// ---------------------------------------------------------------------------
__global__ __launch_bounds__(256) void epilogue_kernel(
    const int* __restrict__ comp,
    const float* __restrict__ out_gamma, const float* __restrict__ out_beta,
    float* __restrict__ attn_base, float* __restrict__ out,
    float* __restrict__ uid_out, int write_uid)
{
    const int c = blockIdx.x >> 2;
    const int h = blockIdx.x & 3;
    const int t = threadIdx.x;
    const int wid  = t >> 5;
    const int lane = t & 31;

    __shared__ int   s_nz;
    __shared__ unsigned char smask[N_];
    __shared__ float swred[8];
    __shared__ float sstat;           // reused: max, then sum
    __shared__ float swacc[8 * 17];

    // ---- dtype detection: int64 iff all odd 32-bit words in the first N_
    // words are zero (values in [0,32); in-bounds for both dtypes). ----
    if (t == 0) s_nz = 0;
    __syncthreads();
    {
        int vz = 0;
        for (int i = t; i < N_/2; i += 256) vz |= comp[2*i + 1];
        if (vz) atomicOr(&s_nz, 1);
    }
    __syncthreads();
    const int is64 = (s_nz == 0);

    // ---- per-node match mask (read comp once) ----
    for (int n = t; n < N_; n += 256) {
        int cid = is64 ? comp[2*n] : comp[n];
        smask[n] = (cid == c);
    }
    __syncthreads();

    // ---- pass 1: max over matching logits of this head ----
    float m = -3.0e38f;
#pragma unroll
    for (int k = 0; k < NL_/256; k++) {
        int j = t + k * 256;
        if (smask[j >> 1]) m = fmaxf(m, g_logits[j * H_ + h]);
    }
    m = warp_max32(m);
    if (lane == 0) swred[wid] = m;
    __syncthreads();
    if (t == 0) {
        float mm = swred[0];
#pragma unroll
        for (int w = 1; w < 8; w++) mm = fmaxf(mm, swred[w]);
        sstat = mm;
    }
    __syncthreads();
    const float mx = sstat;

    // ---- pass 2: exp-sum ----
    float ss = 0.f;
#pragma unroll
    for (int k = 0; k < NL_/256; k++) {
        int j = t + k * 256;
        if (smask[j >> 1]) ss += __expf(g_logits[j * H_ + h] - mx);
    }
    ss = warp_sum32(ss);
    if (lane == 0) swred[wid] = ss;
    __syncthreads();
    if (t == 0) {
        float tot = 0.f;
#pragma unroll
        for (int w = 0; w < 8; w++) tot += swred[w];
        sstat = 1.f / tot;
    }
    __syncthreads();
    const float rinv = sstat;

    // ---- pass 3: normalized attn writes + weighted value accumulation ----
    float* attn_c = attn_base + (size_t)c * NLH;
    float acc[D_];
#pragma unroll
    for (int d = 0; d < D_; d++) acc[d] = 0.f;

#pragma unroll
    for (int k = 0; k < NL_/256; k++) {
        int j = t + k * 256;
        if (smask[j >> 1]) {
            int idx = j * H_ + h;
            float e = __expf(g_logits[idx] - mx) * rinv;
            attn_c[idx] = e;
            const float4* v4 = (const float4*)(g_value + (size_t)idx * D_);
            float4 va = v4[0], vb = v4[1], vc = v4[2], vd = v4[3];
            acc[0]  = fmaf(e, va.x, acc[0]);  acc[1]  = fmaf(e, va.y, acc[1]);
            acc[2]  = fmaf(e, va.z, acc[2]);  acc[3]  = fmaf(e, va.w, acc[3]);
            acc[4]  = fmaf(e, vb.x, acc[4]);  acc[5]  = fmaf(e, vb.y, acc[5]);
            acc[6]  = fmaf(e, vb.z, acc[6]);  acc[7]  = fmaf(e, vb.w, acc[7]);
            acc[8]  = fmaf(e, vc.x, acc[8]);  acc[9]  = fmaf(e, vc.y, acc[9]);
            acc[10] = fmaf(e, vc.z, acc[10]); acc[11] = fmaf(e, vc.w, acc[11]);
            acc[12] = fmaf(e, vd.x, acc[12]); acc[13] = fmaf(e, vd.y, acc[13]);
            acc[14] = fmaf(e, vd.z, acc[14]); acc[15] = fmaf(e, vd.w, acc[15]);
        }
    }

    // ---- per-warp xor-reduction (all lanes end with warp totals) ----
#pragma unroll
    for (int d = 0; d < D_; d++) acc[d] = warp_sum32(acc[d]);
    if (lane < D_) swacc[wid * 17 + lane] = acc[lane];  // lane i stores d=i
    __syncthreads();

    // ---- combine 8 warps + final LayerNorm over d (warp 0) ----
    if (t < 32) {
        int d = t & 15;
        float x = 0.f;
#pragma unroll
        for (int w = 0; w < 8; w++) x += swacc[w * 17 + d];
        float mu = warp_sum16(x) * (1.f/16.f);
        float dl = x - mu;
        float var = warp_sum16(dl * dl) * (1.f/16.f);
        if (t < 16)
            out[c * (H_*D_) + h * D_ + d] =
                fmaf(dl * rsqrtf(var + EPS), out_gamma[d], out_beta[d]);
    }

    if (write_uid && h == 0 && t == 0)
        uid_out[c] = (float)c;
}

// ---------------------------------------------------------------------------
extern "C" void kernel_launch(void* const* d_in, const int* in_sizes, int n_in,
                              void* d_out, int out_size) {
    const float* feat      = (const float*)d_in[0];
    const float* query     = (const float*)d_in[1];
    const float* kw0       = (const float*)d_in[2];
    const float* kb0       = (const float*)d_in[3];
    const float* kw1       = (const float*)d_in[4];
    const float* kb1       = (const float*)d_in[5];
    const float* vw0       = (const float*)d_in[6];
    const float* vb0       = (const float*)d_in[7];
    const float* vw1       = (const float*)d_in[8];
    const float* vb1       = (const float*)d_in[9];
    const float* key_gamma = (const float*)d_in[10];
    const float* key_beta  = (const float*)d_in[11];
    const float* out_gamma = (const float*)d_in[12];
    const float* out_beta  = (const float*)d_in[13];
    const int*   comp      = (const int*)  d_in[14];   // int32 or int64; detected on device

    float* out = (float*)d_out;

    const int SZ_OUT  = C_ * H_ * D_;      // 2048
    const int SZ_ATTN = C_ * NLH;          // 524288
    const int full_attn = (out_size >= SZ_OUT + SZ_ATTN) ? 1 : 0;
    const int full_uid  = (out_size >= SZ_OUT + SZ_ATTN + C_) ? 1 : 0;

    float* attn_base;
    if (full_attn) {
        attn_base = out + SZ_OUT;
    } else {
        void* p = nullptr;
        cudaGetSymbolAddress(&p, g_attn_scratch);
        attn_base = (float*)p;
    }
    // d_out is poisoned before timing; zero the (sparse) attn region first.
    cudaMemsetAsync(attn_base, 0, (size_t)SZ_ATTN * sizeof(float), 0);

    ffn_kernel<<<N_ * L_, 128>>>(feat, query, kw0, kb0, kw1, kb1,
                                 vw0, vb0, vw1, vb1, key_gamma, key_beta);

    float* uid_out = full_uid ? (out + SZ_OUT + SZ_ATTN) : (float*)nullptr;
    epilogue_kernel<<<C_ * H_, 256>>>(comp, out_gamma, out_beta,
                                      attn_base, out, uid_out, full_uid);
}

// round 7
// speedup vs baseline: 1.1644x; 1.0262x over previous
#include <cuda_runtime.h>

#define N_  2048
#define L_  2
#define H_  4
#define D_  16
#define F_  64
#define E_  64
#define C_  32
#define NL_ (N_*L_)             // 4096
#define NLH (N_*L_*H_)          // 16384
#define EPS 1e-5f

#define ET  512                 // epilogue threads
#define EK  (NL_/ET)            // 8 j's per thread
#define EW  (ET/32)             // 16 warps

// Scratch (device globals — no allocation allowed)
__device__ float g_logits[NLH];            // 64 KB
__device__ float g_value [NLH * D_];       // 1 MB
__device__ float g_attn_scratch[C_ * NLH]; // 2 MB fallback if attn not in d_out

// ---------------------------------------------------------------------------
__device__ __forceinline__ float warp_sum16(float v) {
    v += __shfl_xor_sync(0xffffffffu, v, 1);
    v += __shfl_xor_sync(0xffffffffu, v, 2);
    v += __shfl_xor_sync(0xffffffffu, v, 4);
    v += __shfl_xor_sync(0xffffffffu, v, 8);
    return v;
}

__device__ __forceinline__ float warp_sum32(float v) {
    v += __shfl_xor_sync(0xffffffffu, v, 16);
    return warp_sum16(v);
}

__device__ __forceinline__ float warp_max32(float v) {
    v = fmaxf(v, __shfl_xor_sync(0xffffffffu, v, 16));
    v = fmaxf(v, __shfl_xor_sync(0xffffffffu, v, 8));
    v = fmaxf(v, __shfl_xor_sync(0xffffffffu, v, 4));
    v = fmaxf(v, __shfl_xor_sync(0xffffffffu, v, 2));
    v = fmaxf(v, __shfl_xor_sync(0xffffffffu, v, 1));
    return v;
}

__device__ __forceinline__ float dot4(float4 w, float4 f) {
    return fmaf(w.x, f.x, fmaf(w.y, f.y, fmaf(w.z, f.z, w.w * f.w)));
}

// ---------------------------------------------------------------------------
// Kernel 1: per-node FFNs, key + value paths interleaved. One warp per (n,l,h).
// Per step: one LDG.128 across warp = 512B contiguous (w0, two rows) per path,
// one LDG.32 across warp = one 128B line (w1, two rows) per path.
// ---------------------------------------------------------------------------
__global__ __launch_bounds__(128) void ffn_kernel(
    const float* __restrict__ feat,  const float* __restrict__ query,
    const float* __restrict__ kw0,   const float* __restrict__ kb0,
    const float* __restrict__ kw1,   const float* __restrict__ kb1,
    const float* __restrict__ vw0,   const float* __restrict__ vb0,
    const float* __restrict__ vw1,   const float* __restrict__ vb1,
    const float* __restrict__ key_gamma, const float* __restrict__ key_beta)
{
    const int nl   = blockIdx.x;
    const int wid  = threadIdx.x >> 5;
    const int lane = threadIdx.x & 31;
    const int l16  = lane & 15;
    const int half = lane >> 4;
    const int nlh  = nl * H_ + wid;

    const float4 f4 = ((const float4*)(feat + (size_t)nl * E_))[l16];
    const float gd = key_gamma[l16];
    const float bd = key_beta [l16];

    const size_t o0 = (size_t)nlh * (F_ * E_);
    const size_t o1 = (size_t)nlh * (F_ * D_);
    const size_t ob = (size_t)nlh * F_;
    const size_t od = (size_t)nlh * D_;

    const float* kw0p = kw0 + o0 + half * E_ + l16 * 4;
    const float* vw0p = vw0 + o0 + half * E_ + l16 * 4;
    const float* kw1p = kw1 + o1 + half * D_ + l16;
    const float* vw1p = vw1 + o1 + half * D_ + l16;

    const float kb0a = kb0[ob + lane],      kb0b = kb0[ob + 32 + lane];
    const float vb0a = vb0[ob + lane],      vb0b = vb0[ob + 32 + lane];

    float accK = 0.f, accV = 0.f;
#pragma unroll
    for (int s = 0; s < 32; s++) {
        float4 wk = __ldcs((const float4*)(kw0p + s * 2 * E_));
        float4 wv = __ldcs((const float4*)(vw0p + s * 2 * E_));
        float w1k = __ldcs(kw1p + s * 2 * D_);
        float w1v = __ldcs(vw1p + s * 2 * D_);

        float tk = warp_sum16(dot4(wk, f4));   // two independent shfl chains
        float tv = warp_sum16(dot4(wv, f4));

        float bK = __shfl_sync(0xffffffffu, (s < 16) ? kb0a : kb0b, 2*s + half);
        float bV = __shfl_sync(0xffffffffu, (s < 16) ? vb0a : vb0b, 2*s + half);

        accK = fmaf(fmaxf(tk + bK, 0.f), w1k, accK);
        accV = fmaf(fmaxf(tv + bV, 0.f), w1v, accV);
    }

    float xK = accK + __shfl_xor_sync(0xffffffffu, accK, 16) + kb1[od + l16];
    float xV = accV + __shfl_xor_sync(0xffffffffu, accV, 16) + vb1[od + l16];

    // LayerNorm over 16 d-values (both halves replicated); ref reuses key LN
    float muK  = warp_sum16(xK) * (1.f/16.f);
    float dlK  = xK - muK;
    float varK = warp_sum16(dlK * dlK) * (1.f/16.f);
    float kln  = fmaf(dlK * rsqrtf(varK + EPS), gd, bd);

    float muV  = warp_sum16(xV) * (1.f/16.f);
    float dlV  = xV - muV;
    float varV = warp_sum16(dlV * dlV) * (1.f/16.f);
    float vln  = fmaf(dlV * rsqrtf(varV + EPS), gd, bd);

    float p = warp_sum16(kln * query[od + l16]);
    if (lane == 0) g_logits[nlh] = p;
    if (lane < D_) g_value[od + lane] = vln;
}

// ---------------------------------------------------------------------------
// Kernel 2 (fused epilogue): one block per (c,h); zero cross-block deps.
// Logits loaded ONCE unconditionally into registers (pipelined), exp computed
// once; mask applied arithmetically. 512 threads for latency hiding.
// ---------------------------------------------------------------------------
__global__ __launch_bounds__(ET) void epilogue_kernel(
    const int* __restrict__ comp,
    const float* __restrict__ out_gamma, const float* __restrict__ out_beta,
    float* __restrict__ attn_base, float* __restrict__ out,
    float* __restrict__ uid_out, int write_uid)
{
    const int c = blockIdx.x >> 2;
    const int h = blockIdx.x & 3;
    const int t = threadIdx.x;
    const int wid  = t >> 5;
    const int lane = t & 31;

    __shared__ int   s_nz;
    __shared__ unsigned char smask[N_];
    __shared__ float swred[EW];
    __shared__ float sstat;           // reused: max, then rinv
    __shared__ float swacc[EW * 17];

    // ---- dtype detection: int64 iff all odd 32-bit words in the first N_
    // words are zero (values in [0,32); in-bounds for both dtypes). ----
    if (t == 0) s_nz = 0;
    __syncthreads();
    {
        int vz = 0;
        for (int i = t; i < N_/2; i += ET) vz |= comp[2*i + 1];
        if (vz) atomicOr(&s_nz, 1);
    }
    __syncthreads();
    const int is64 = (s_nz == 0);

    // ---- per-node match mask (read comp once) ----
    for (int n = t; n < N_; n += ET) {
        int cid = is64 ? comp[2*n] : comp[n];
        smask[n] = (cid == c);
    }
    __syncthreads();

    // ---- single logits sweep into registers (independent, pipelined) ----
    float lg[EK];
    int   mk[EK];
#pragma unroll
    for (int k = 0; k < EK; k++) {
        int j = t + k * ET;
        lg[k] = g_logits[j * H_ + h];     // unconditional -> no LDS/pred chain
        mk[k] = smask[j >> 1];
    }

    // ---- masked max ----
    float m = -3.0e38f;
#pragma unroll
    for (int k = 0; k < EK; k++) m = fmaxf(m, mk[k] ? lg[k] : -3.0e38f);
    m = warp_max32(m);
    if (lane == 0) swred[wid] = m;
    __syncthreads();
    if (t == 0) {
        float mm = swred[0];
#pragma unroll
        for (int w = 1; w < EW; w++) mm = fmaxf(mm, swred[w]);
        sstat = mm;
    }
    __syncthreads();
    const float mx = sstat;

    // ---- exp once, masked sum ----
    float e[EK];
    float ss = 0.f;
#pragma unroll
    for (int k = 0; k < EK; k++) {
        e[k] = mk[k] ? __expf(lg[k] - mx) : 0.f;
        ss += e[k];
    }
    ss = warp_sum32(ss);
    if (lane == 0) swred[wid] = ss;
    __syncthreads();
    if (t == 0) {
        float tot = 0.f;
#pragma unroll
        for (int w = 0; w < EW; w++) tot += swred[w];
        sstat = 1.f / tot;
    }
    __syncthreads();
    const float rinv = sstat;

    // ---- attn writes + weighted value accumulation (matches only) ----
    float* attn_c = attn_base + (size_t)c * NLH;
    float acc[D_];
#pragma unroll
    for (int d = 0; d < D_; d++) acc[d] = 0.f;

#pragma unroll
    for (int k = 0; k < EK; k++) {
        if (mk[k]) {
            int idx = (t + k * ET) * H_ + h;
            float w = e[k] * rinv;
            attn_c[idx] = w;
            const float4* v4 = (const float4*)(g_value + (size_t)idx * D_);
            float4 va = v4[0], vb = v4[1], vc = v4[2], vd = v4[3];
            acc[0]  = fmaf(w, va.x, acc[0]);  acc[1]  = fmaf(w, va.y, acc[1]);
            acc[2]  = fmaf(w, va.z, acc[2]);  acc[3]  = fmaf(w, va.w, acc[3]);
            acc[4]  = fmaf(w, vb.x, acc[4]);  acc[5]  = fmaf(w, vb.y, acc[5]);
            acc[6]  = fmaf(w, vb.z, acc[6]);  acc[7]  = fmaf(w, vb.w, acc[7]);
            acc[8]  = fmaf(w, vc.x, acc[8]);  acc[9]  = fmaf(w, vc.y, acc[9]);
            acc[10] = fmaf(w, vc.z, acc[10]); acc[11] = fmaf(w, vc.w, acc[11]);
            acc[12] = fmaf(w, vd.x, acc[12]); acc[13] = fmaf(w, vd.y, acc[13]);
            acc[14] = fmaf(w, vd.z, acc[14]); acc[15] = fmaf(w, vd.w, acc[15]);
        }
    }

    // ---- per-warp reduction, then block combine ----
#pragma unroll
    for (int d = 0; d < D_; d++) acc[d] = warp_sum32(acc[d]);
    if (lane < D_) swacc[wid * 17 + lane] = acc[lane];
    __syncthreads();

    // ---- combine EW warps + final LayerNorm over d (warp 0) ----
    if (t < 32) {
        int d = t & 15;
        float x = 0.f;
#pragma unroll
        for (int w = 0; w < EW; w++) x += swacc[w * 17 + d];
        float mu = warp_sum16(x) * (1.f/16.f);
        float dl = x - mu;
        float var = warp_sum16(dl * dl) * (1.f/16.f);
        if (t < 16)
            out[c * (H_*D_) + h * D_ + d] =
                fmaf(dl * rsqrtf(var + EPS), out_gamma[d], out_beta[d]);
    }

    if (write_uid && h == 0 && t == 0)
        uid_out[c] = (float)c;
}

// ---------------------------------------------------------------------------
extern "C" void kernel_launch(void* const* d_in, const int* in_sizes, int n_in,
                              void* d_out, int out_size) {
    const float* feat      = (const float*)d_in[0];
    const float* query     = (const float*)d_in[1];
    const float* kw0       = (const float*)d_in[2];
    const float* kb0       = (const float*)d_in[3];
    const float* kw1       = (const float*)d_in[4];
    const float* kb1       = (const float*)d_in[5];
    const float* vw0       = (const float*)d_in[6];
    const float* vb0       = (const float*)d_in[7];
    const float* vw1       = (const float*)d_in[8];
    const float* vb1       = (const float*)d_in[9];
    const float* key_gamma = (const float*)d_in[10];
    const float* key_beta  = (const float*)d_in[11];
    const float* out_gamma = (const float*)d_in[12];
    const float* out_beta  = (const float*)d_in[13];
    const int*   comp      = (const int*)  d_in[14];   // int32 or int64; detected on device

    float* out = (float*)d_out;

    const int SZ_OUT  = C_ * H_ * D_;      // 2048
    const int SZ_ATTN = C_ * NLH;          // 524288
    const int full_attn = (out_size >= SZ_OUT + SZ_ATTN) ? 1 : 0;
    const int full_uid  = (out_size >= SZ_OUT + SZ_ATTN + C_) ? 1 : 0;

    float* attn_base;
    if (full_attn) {
        attn_base = out + SZ_OUT;
    } else {
        void* p = nullptr;
        cudaGetSymbolAddress(&p, g_attn_scratch);
        attn_base = (float*)p;
    }
    // d_out is poisoned before timing; zero the (sparse) attn region first.
    cudaMemsetAsync(attn_base, 0, (size_t)SZ_ATTN * sizeof(float), 0);

    ffn_kernel<<<N_ * L_, 128>>>(feat, query, kw0, kb0, kw1, kb1,
                                 vw0, vb0, vw1, vb1, key_gamma, key_beta);

    float* uid_out = full_uid ? (out + SZ_OUT + SZ_ATTN) : (float*)nullptr;
    epilogue_kernel<<<C_ * H_, ET>>>(comp, out_gamma, out_beta,
                                     attn_base, out, uid_out, full_uid);
}

// round 8
// speedup vs baseline: 1.2014x; 1.0317x over previous
#include <cuda_runtime.h>

#define N_  2048
#define L_  2
#define H_  4
#define D_  16
#define F_  64
#define E_  64
#define C_  32
#define NL_ (N_*L_)             // 4096
#define NLH (N_*L_*H_)          // 16384
#define EPS 1e-5f

#define ET  512                 // epilogue threads
#define EK  (NL_/ET)            // 8 j's per thread
#define EW  (ET/32)             // 16 warps

// Scratch (device globals — no allocation allowed)
__device__ float g_logits[NLH];            // 64 KB
__device__ float g_value [NLH * D_];       // 1 MB
__device__ float g_attn_scratch[C_ * NLH]; // 2 MB fallback if attn not in d_out
__device__ int   g_comp[N_];               // normalized int32 component ids

// ---------------------------------------------------------------------------
__device__ __forceinline__ float warp_sum16(float v) {
    v += __shfl_xor_sync(0xffffffffu, v, 1);
    v += __shfl_xor_sync(0xffffffffu, v, 2);
    v += __shfl_xor_sync(0xffffffffu, v, 4);
    v += __shfl_xor_sync(0xffffffffu, v, 8);
    return v;
}

__device__ __forceinline__ float warp_sum32(float v) {
    v += __shfl_xor_sync(0xffffffffu, v, 16);
    return warp_sum16(v);
}

__device__ __forceinline__ float warp_max32(float v) {
    v = fmaxf(v, __shfl_xor_sync(0xffffffffu, v, 16));
    v = fmaxf(v, __shfl_xor_sync(0xffffffffu, v, 8));
    v = fmaxf(v, __shfl_xor_sync(0xffffffffu, v, 4));
    v = fmaxf(v, __shfl_xor_sync(0xffffffffu, v, 2));
    v = fmaxf(v, __shfl_xor_sync(0xffffffffu, v, 1));
    return v;
}

__device__ __forceinline__ float dot4(float4 w, float4 f) {
    return fmaf(w.x, f.x, fmaf(w.y, f.y, fmaf(w.z, f.z, w.w * f.w)));
}

// ---------------------------------------------------------------------------
// Kernel 1: per-node FFNs, key + value paths interleaved. One warp per (n,l,h).
// Per step: one LDG.128 across warp = 512B contiguous (w0, two rows) per path,
// one LDG.32 across warp = one 128B line (w1, two rows) per path.
// Blocks 0..15 additionally normalize component ids into g_comp at the end
// (dtype auto-detected); hidden in the launch tail.
// ---------------------------------------------------------------------------
__global__ __launch_bounds__(128) void ffn_kernel(
    const float* __restrict__ feat,  const float* __restrict__ query,
    const float* __restrict__ kw0,   const float* __restrict__ kb0,
    const float* __restrict__ kw1,   const float* __restrict__ kb1,
    const float* __restrict__ vw0,   const float* __restrict__ vb0,
    const float* __restrict__ vw1,   const float* __restrict__ vb1,
    const float* __restrict__ key_gamma, const float* __restrict__ key_beta,
    const int* __restrict__ comp)
{
    const int nl   = blockIdx.x;
    const int wid  = threadIdx.x >> 5;
    const int lane = threadIdx.x & 31;
    const int l16  = lane & 15;
    const int half = lane >> 4;
    const int nlh  = nl * H_ + wid;

    const float4 f4 = ((const float4*)(feat + (size_t)nl * E_))[l16];
    const float gd = key_gamma[l16];
    const float bd = key_beta [l16];

    const size_t o0 = (size_t)nlh * (F_ * E_);
    const size_t o1 = (size_t)nlh * (F_ * D_);
    const size_t ob = (size_t)nlh * F_;
    const size_t od = (size_t)nlh * D_;

    const float* kw0p = kw0 + o0 + half * E_ + l16 * 4;
    const float* vw0p = vw0 + o0 + half * E_ + l16 * 4;
    const float* kw1p = kw1 + o1 + half * D_ + l16;
    const float* vw1p = vw1 + o1 + half * D_ + l16;

    const float kb0a = kb0[ob + lane],      kb0b = kb0[ob + 32 + lane];
    const float vb0a = vb0[ob + lane],      vb0b = vb0[ob + 32 + lane];

    float accK = 0.f, accV = 0.f;
#pragma unroll
    for (int s = 0; s < 32; s++) {
        float4 wk = __ldcs((const float4*)(kw0p + s * 2 * E_));
        float4 wv = __ldcs((const float4*)(vw0p + s * 2 * E_));
        float w1k = __ldcs(kw1p + s * 2 * D_);
        float w1v = __ldcs(vw1p + s * 2 * D_);

        float tk = warp_sum16(dot4(wk, f4));   // two independent shfl chains
        float tv = warp_sum16(dot4(wv, f4));

        float bK = __shfl_sync(0xffffffffu, (s < 16) ? kb0a : kb0b, 2*s + half);
        float bV = __shfl_sync(0xffffffffu, (s < 16) ? vb0a : vb0b, 2*s + half);

        accK = fmaf(fmaxf(tk + bK, 0.f), w1k, accK);
        accV = fmaf(fmaxf(tv + bV, 0.f), w1v, accV);
    }

    float xK = accK + __shfl_xor_sync(0xffffffffu, accK, 16) + kb1[od + l16];
    float xV = accV + __shfl_xor_sync(0xffffffffu, accV, 16) + vb1[od + l16];

    // LayerNorm over 16 d-values (both halves replicated); ref reuses key LN
    float muK  = warp_sum16(xK) * (1.f/16.f);
    float dlK  = xK - muK;
    float varK = warp_sum16(dlK * dlK) * (1.f/16.f);
    float kln  = fmaf(dlK * rsqrtf(varK + EPS), gd, bd);

    float muV  = warp_sum16(xV) * (1.f/16.f);
    float dlV  = xV - muV;
    float varV = warp_sum16(dlV * dlV) * (1.f/16.f);
    float vln  = fmaf(dlV * rsqrtf(varV + EPS), gd, bd);

    float p = warp_sum16(kln * query[od + l16]);
    if (lane == 0) g_logits[nlh] = p;
    if (lane < D_) g_value[od + lane] = vln;

    // ---- comp normalization (blocks 0..15, 128 nodes each) ----
    if (blockIdx.x < 16) {
        __shared__ int s_nz;
        if (threadIdx.x == 0) s_nz = 0;
        __syncthreads();
        // dtype: int64 iff all odd 32-bit words in the first N_ words are 0
        int vz = 0;
        for (int i = threadIdx.x; i < N_/2; i += 128) vz |= comp[2*i + 1];
        if (__any_sync(0xffffffffu, vz != 0) && lane == 0) atomicOr(&s_nz, 1);
        __syncthreads();
        const int is64 = (s_nz == 0);
        const int base = blockIdx.x * 128;
        const int n = base + threadIdx.x;
        g_comp[n] = is64 ? comp[2*n] : comp[n];
    }
}

// ---------------------------------------------------------------------------
// Kernel 2 (fused epilogue): one block per (c,h); zero cross-block deps.
// Flat pipelined front: 8 logit + 4 comp loads per thread, mask arithmetic
// from registers; no smem mask, no dtype detection.
// ---------------------------------------------------------------------------
__global__ __launch_bounds__(ET) void epilogue_kernel(
    const float* __restrict__ out_gamma, const float* __restrict__ out_beta,
    float* __restrict__ attn_base, float* __restrict__ out,
    float* __restrict__ uid_out, int write_uid)
{
    const int c = blockIdx.x >> 2;
    const int h = blockIdx.x & 3;
    const int t = threadIdx.x;
    const int wid  = t >> 5;
    const int lane = t & 31;

    __shared__ float swred[EW];
    __shared__ float sstat;           // reused: max, then rinv
    __shared__ float swacc[EW * 17];

    // ---- single pipelined sweep: logits + comp ids into registers ----
    float lg[EK];
    int   mk[EK];
#pragma unroll
    for (int k = 0; k < EK; k++) {
        int j = t + k * ET;
        lg[k] = g_logits[j * H_ + h];
        mk[k] = (g_comp[j >> 1] == c);
    }

    // ---- masked max ----
    float m = -3.0e38f;
#pragma unroll
    for (int k = 0; k < EK; k++) m = fmaxf(m, mk[k] ? lg[k] : -3.0e38f);
    m = warp_max32(m);
    if (lane == 0) swred[wid] = m;
    __syncthreads();
    if (t == 0) {
        float mm = swred[0];
#pragma unroll
        for (int w = 1; w < EW; w++) mm = fmaxf(mm, swred[w]);
        sstat = mm;
    }
    __syncthreads();
    const float mx = sstat;

    // ---- exp once, masked sum ----
    float e[EK];
    float ss = 0.f;
#pragma unroll
    for (int k = 0; k < EK; k++) {
        e[k] = mk[k] ? __expf(lg[k] - mx) : 0.f;
        ss += e[k];
    }
    ss = warp_sum32(ss);
    if (lane == 0) swred[wid] = ss;
    __syncthreads();
    if (t == 0) {
        float tot = 0.f;
#pragma unroll
        for (int w = 0; w < EW; w++) tot += swred[w];
        sstat = 1.f / tot;
    }
    __syncthreads();
    const float rinv = sstat;

    // ---- attn writes + weighted value accumulation (matches only) ----
    float* attn_c = attn_base + (size_t)c * NLH;
    float acc[D_];
#pragma unroll
    for (int d = 0; d < D_; d++) acc[d] = 0.f;

#pragma unroll
    for (int k = 0; k < EK; k++) {
        if (mk[k]) {
            int idx = (t + k * ET) * H_ + h;
            float w = e[k] * rinv;
            attn_c[idx] = w;
            const float4* v4 = (const float4*)(g_value + (size_t)idx * D_);
            float4 va = v4[0], vb = v4[1], vc = v4[2], vd = v4[3];
            acc[0]  = fmaf(w, va.x, acc[0]);  acc[1]  = fmaf(w, va.y, acc[1]);
            acc[2]  = fmaf(w, va.z, acc[2]);  acc[3]  = fmaf(w, va.w, acc[3]);
            acc[4]  = fmaf(w, vb.x, acc[4]);  acc[5]  = fmaf(w, vb.y, acc[5]);
            acc[6]  = fmaf(w, vb.z, acc[6]);  acc[7]  = fmaf(w, vb.w, acc[7]);
            acc[8]  = fmaf(w, vc.x, acc[8]);  acc[9]  = fmaf(w, vc.y, acc[9]);
            acc[10] = fmaf(w, vc.z, acc[10]); acc[11] = fmaf(w, vc.w, acc[11]);
            acc[12] = fmaf(w, vd.x, acc[12]); acc[13] = fmaf(w, vd.y, acc[13]);
            acc[14] = fmaf(w, vd.z, acc[14]); acc[15] = fmaf(w, vd.w, acc[15]);
        }
    }

    // ---- per-warp reduction, then block combine ----
#pragma unroll
    for (int d = 0; d < D_; d++) acc[d] = warp_sum32(acc[d]);
    if (lane < D_) swacc[wid * 17 + lane] = acc[lane];
    __syncthreads();

    // ---- combine EW warps + final LayerNorm over d (warp 0) ----
    if (t < 32) {
        int d = t & 15;
        float x = 0.f;
#pragma unroll
        for (int w = 0; w < EW; w++) x += swacc[w * 17 + d];
        float mu = warp_sum16(x) * (1.f/16.f);
        float dl = x - mu;
        float var = warp_sum16(dl * dl) * (1.f/16.f);
        if (t < 16)
            out[c * (H_*D_) + h * D_ + d] =
                fmaf(dl * rsqrtf(var + EPS), out_gamma[d], out_beta[d]);
    }

    if (write_uid && h == 0 && t == 0)
        uid_out[c] = (float)c;
}

// ---------------------------------------------------------------------------
extern "C" void kernel_launch(void* const* d_in, const int* in_sizes, int n_in,
                              void* d_out, int out_size) {
    const float* feat      = (const float*)d_in[0];
    const float* query     = (const float*)d_in[1];
    const float* kw0       = (const float*)d_in[2];
    const float* kb0       = (const float*)d_in[3];
    const float* kw1       = (const float*)d_in[4];
    const float* kb1       = (const float*)d_in[5];
    const float* vw0       = (const float*)d_in[6];
    const float* vb0       = (const float*)d_in[7];
    const float* vw1       = (const float*)d_in[8];
    const float* vb1       = (const float*)d_in[9];
    const float* key_gamma = (const float*)d_in[10];
    const float* key_beta  = (const float*)d_in[11];
    const float* out_gamma = (const float*)d_in[12];
    const float* out_beta  = (const float*)d_in[13];
    const int*   comp      = (const int*)  d_in[14];   // int32 or int64; detected on device

    float* out = (float*)d_out;

    const int SZ_OUT  = C_ * H_ * D_;      // 2048
    const int SZ_ATTN = C_ * NLH;          // 524288
    const int full_attn = (out_size >= SZ_OUT + SZ_ATTN) ? 1 : 0;
    const int full_uid  = (out_size >= SZ_OUT + SZ_ATTN + C_) ? 1 : 0;

    float* attn_base;
    if (full_attn) {
        attn_base = out + SZ_OUT;
    } else {
        void* p = nullptr;
        cudaGetSymbolAddress(&p, g_attn_scratch);
        attn_base = (float*)p;
    }
    // d_out is poisoned before timing; zero the (sparse) attn region first.
    cudaMemsetAsync(attn_base, 0, (size_t)SZ_ATTN * sizeof(float), 0);

    ffn_kernel<<<N_ * L_, 128>>>(feat, query, kw0, kb0, kw1, kb1,
                                 vw0, vb0, vw1, vb1, key_gamma, key_beta, comp);

    float* uid_out = full_uid ? (out + SZ_OUT + SZ_ATTN) : (float*)nullptr;
    epilogue_kernel<<<C_ * H_, ET>>>(out_gamma, out_beta,
                                     attn_base, out, uid_out, full_uid);
}